// round 4
// baseline (speedup 1.0000x reference)
#include <cuda_runtime.h>
#include <cuda_bf16.h>
#include <math.h>

#define NMAX 100000
#define EMAX 1600000
#define D    128
#define D4   32
#define NG   64
#define NEG_SLOPE 0.2f

// ---------------- scratch (static device globals; no allocs allowed) ----------------
__device__ float g_feat[NMAX * D];     // x @ W for current layer
__device__ float g_x[NMAX * D];        // layer output / next layer input
__device__ float g_el[NMAX];
__device__ float g_er[NMAX];
__device__ float g_inv[NMAX];          // 1 / softmax denominator per dst
__device__ int   g_counts[NMAX];
__device__ int   g_offsets[NMAX + 1];
__device__ int   g_cursor[NMAX];
__device__ int   g_esrc[EMAX];         // src node of each edge, sorted by dst
__device__ float g_ew[EMAX];           // per-edge scratch: e, then exp(e-m)
__device__ float g_hg[NG * D];
__device__ int   g_gcnt[NG];

// ---------------- zeroing ----------------
__global__ void zero_kernel(int n_nodes) {
    int i = blockIdx.x * blockDim.x + threadIdx.x;
    int stride = gridDim.x * blockDim.x;
    for (int k = i; k < n_nodes; k += stride) g_counts[k] = 0;
    for (int k = i; k < NG * D; k += stride) g_hg[k] = 0.0f;
}

// ---------------- CSR build ----------------
__global__ void hist_kernel(const int* __restrict__ dst, int E) {
    int i = blockIdx.x * blockDim.x + threadIdx.x;
    int stride = gridDim.x * blockDim.x;
    for (int e = i; e < E; e += stride) atomicAdd(&g_counts[dst[e]], 1);
}

__global__ void scan_kernel(int n_nodes) {
    __shared__ int sums[1024];
    int t = threadIdx.x;
    int chunk = (n_nodes + 1023) / 1024;
    int begin = t * chunk;
    int end = begin + chunk; if (end > n_nodes) end = n_nodes;
    int s = 0;
    for (int i = begin; i < end; i++) s += g_counts[i];
    sums[t] = s;
    __syncthreads();
    for (int off = 1; off < 1024; off <<= 1) {
        int v = (t >= off) ? sums[t - off] : 0;
        __syncthreads();
        sums[t] += v;
        __syncthreads();
    }
    int run = (t > 0) ? sums[t - 1] : 0;
    for (int i = begin; i < end; i++) {
        int c = g_counts[i];
        g_offsets[i] = run;
        g_cursor[i]  = run;
        run += c;
    }
    if (t == 1023) g_offsets[n_nodes] = sums[1023];
}

__global__ void scatter_kernel(const int* __restrict__ src, const int* __restrict__ dst, int E) {
    int i = blockIdx.x * blockDim.x + threadIdx.x;
    int stride = gridDim.x * blockDim.x;
    for (int e = i; e < E; e += stride) {
        int d = dst[e];
        int pos = atomicAdd(&g_cursor[d], 1);
        g_esrc[pos] = src[e];
    }
}

// ---------------- GEMM: out[N,128] = X[N,128] @ W[128,128] ----------------
__global__ __launch_bounds__(256) void gemm_kernel(const float* __restrict__ X,
                                                   const float* __restrict__ W,
                                                   float* __restrict__ out, int n_rows) {
    extern __shared__ float sm[];
    float* Ws = sm;            // 128*128 floats = 64KB
    float* Xs = sm + D * D;    // 64*128 floats  = 32KB
    int tid = threadIdx.x;
    int row0 = blockIdx.x * 64;

    for (int i = tid; i < (D * D) / 4; i += 256)
        ((float4*)Ws)[i] = ((const float4*)W)[i];
    for (int i = tid; i < (64 * D) / 4; i += 256) {
        int r = i / D4;
        int c = i % D4;
        int gr = row0 + r;
        float4 v = make_float4(0.f, 0.f, 0.f, 0.f);
        if (gr < n_rows) v = ((const float4*)X)[gr * D4 + c];
        ((float4*)Xs)[i] = v;
    }
    __syncthreads();

    int tx = tid & 15;
    int ty = tid >> 4;
    int c0 = tx * 8;
    float acc[4][8];
#pragma unroll
    for (int r = 0; r < 4; r++)
#pragma unroll
        for (int c = 0; c < 8; c++) acc[r][c] = 0.f;

#pragma unroll 4
    for (int k = 0; k < D; k++) {
        float a0 = Xs[(ty * 4 + 0) * D + k];
        float a1 = Xs[(ty * 4 + 1) * D + k];
        float a2 = Xs[(ty * 4 + 2) * D + k];
        float a3 = Xs[(ty * 4 + 3) * D + k];
        float4 b0 = *(float4*)&Ws[k * D + c0];
        float4 b1 = *(float4*)&Ws[k * D + c0 + 4];
        float bb[8] = {b0.x, b0.y, b0.z, b0.w, b1.x, b1.y, b1.z, b1.w};
#pragma unroll
        for (int c = 0; c < 8; c++) {
            acc[0][c] += a0 * bb[c];
            acc[1][c] += a1 * bb[c];
            acc[2][c] += a2 * bb[c];
            acc[3][c] += a3 * bb[c];
        }
    }

#pragma unroll
    for (int r = 0; r < 4; r++) {
        int gr = row0 + ty * 4 + r;
        if (gr < n_rows) {
            float4 v0 = make_float4(acc[r][0], acc[r][1], acc[r][2], acc[r][3]);
            float4 v1 = make_float4(acc[r][4], acc[r][5], acc[r][6], acc[r][7]);
            ((float4*)out)[gr * D4 + tx * 2 + 0] = v0;
            ((float4*)out)[gr * D4 + tx * 2 + 1] = v1;
        }
    }
}

// ---------------- el/er: per-node dot products ----------------
__global__ __launch_bounds__(256) void el_er_kernel(const float* __restrict__ feat,
                             const float* __restrict__ al, const float* __restrict__ ar,
                             int n_nodes) {
    int w = (blockIdx.x * blockDim.x + threadIdx.x) >> 5;
    int lane = threadIdx.x & 31;
    if (w >= n_nodes) return;
    float4 f = ((const float4*)feat)[w * D4 + lane];
    float4 a = ((const float4*)al)[lane];
    float4 b = ((const float4*)ar)[lane];
    float sl = f.x * a.x + f.y * a.y + f.z * a.z + f.w * a.w;
    float sr = f.x * b.x + f.y * b.y + f.z * b.z + f.w * b.w;
#pragma unroll
    for (int o = 16; o > 0; o >>= 1) {
        sl += __shfl_xor_sync(0xffffffffu, sl, o);
        sr += __shfl_xor_sync(0xffffffffu, sr, o);
    }
    if (lane == 0) { g_el[w] = sl; g_er[w] = sr; }
}

// ---------------- attention stats: per-dst max + softmax denominator ----------------
// Warp per dst node. Pass A: e = leaky(el[src]+er[dst]) cached to g_ew, warp max.
// Pass B: exp(e - m) written back to g_ew, warp sum -> g_inv = 1/sum.
__global__ __launch_bounds__(256) void stats_kernel(int n_nodes) {
    int w = (blockIdx.x * blockDim.x + threadIdx.x) >> 5;
    int lane = threadIdx.x & 31;
    if (w >= n_nodes) return;
    int start = g_offsets[w];
    int end = g_offsets[w + 1];
    if (end == start) return;
    float erd = g_er[w];

    float m = -1e30f;
    for (int i = start + lane; i < end; i += 32) {
        int s = g_esrc[i];
        float e = g_el[s] + erd;
        e = e > 0.f ? e : NEG_SLOPE * e;
        g_ew[i] = e;
        m = fmaxf(m, e);
    }
#pragma unroll
    for (int o = 16; o > 0; o >>= 1) m = fmaxf(m, __shfl_xor_sync(0xffffffffu, m, o));

    float ss = 0.f;
    for (int i = start + lane; i < end; i += 32) {
        float ex = __expf(g_ew[i] - m);
        g_ew[i] = ex;
        ss += ex;
    }
#pragma unroll
    for (int o = 16; o > 0; o >>= 1) ss += __shfl_xor_sync(0xffffffffu, ss, o);
    if (lane == 0) g_inv[w] = 1.0f / ss;
}

// ---------------- weighted SpMM: out[dst] = relu((sum_e w_e * feat[src_e]) * inv + b) ----------------
// Warp per dst node; edge meta via uniform broadcast loads; 4-edge manual unroll for MLP.
__global__ __launch_bounds__(256) void spmm_kernel(const float* __restrict__ feat,
                                                   const float* __restrict__ bias,
                                                   float* __restrict__ out, int n_nodes) {
    int w = (blockIdx.x * blockDim.x + threadIdx.x) >> 5;
    int lane = threadIdx.x & 31;
    if (w >= n_nodes) return;
    int start = g_offsets[w];
    int end = g_offsets[w + 1];

    const float4* f4 = (const float4*)feat;
    float4 acc = make_float4(0.f, 0.f, 0.f, 0.f);

    int i = start;
    for (; i + 4 <= end; i += 4) {
        int s0 = g_esrc[i + 0];
        int s1 = g_esrc[i + 1];
        int s2 = g_esrc[i + 2];
        int s3 = g_esrc[i + 3];
        float w0 = g_ew[i + 0];
        float w1 = g_ew[i + 1];
        float w2 = g_ew[i + 2];
        float w3 = g_ew[i + 3];
        float4 f0 = f4[s0 * D4 + lane];
        float4 f1 = f4[s1 * D4 + lane];
        float4 f2 = f4[s2 * D4 + lane];
        float4 f3 = f4[s3 * D4 + lane];
        acc.x += w0 * f0.x + w1 * f1.x + w2 * f2.x + w3 * f3.x;
        acc.y += w0 * f0.y + w1 * f1.y + w2 * f2.y + w3 * f3.y;
        acc.z += w0 * f0.z + w1 * f1.z + w2 * f2.z + w3 * f3.z;
        acc.w += w0 * f0.w + w1 * f1.w + w2 * f2.w + w3 * f3.w;
    }
    for (; i < end; i++) {
        int s = g_esrc[i];
        float ww = g_ew[i];
        float4 f = f4[s * D4 + lane];
        acc.x += ww * f.x;
        acc.y += ww * f.y;
        acc.z += ww * f.z;
        acc.w += ww * f.w;
    }

    float4 b = ((const float4*)bias)[lane];
    float4 o4;
    if (end > start) {
        float inv = g_inv[w];
        o4.x = fmaxf(acc.x * inv + b.x, 0.f);
        o4.y = fmaxf(acc.y * inv + b.y, 0.f);
        o4.z = fmaxf(acc.z * inv + b.z, 0.f);
        o4.w = fmaxf(acc.w * inv + b.w, 0.f);
    } else {
        o4.x = fmaxf(b.x, 0.f);
        o4.y = fmaxf(b.y, 0.f);
        o4.z = fmaxf(b.z, 0.f);
        o4.w = fmaxf(b.w, 0.f);
    }
    ((float4*)out)[w * D4 + lane] = o4;
}

// ---------------- pooling: graph_id is sorted, running per-block accumulate ----------------
__global__ void pool_kernel(const float* __restrict__ x, const int* __restrict__ gid,
                            int n_nodes) {
    int t = threadIdx.x;          // 0..127, one feature column each
    int n0 = blockIdx.x * 256;
    float acc = 0.f;
    int cur = -1;
    for (int i = 0; i < 256; i++) {
        int n = n0 + i;
        if (n >= n_nodes) break;
        int g = gid[n];
        if (g != cur) {
            if (cur >= 0) atomicAdd(&g_hg[cur * D + t], acc);
            acc = 0.f;
            cur = g;
        }
        acc += x[n * D + t];
    }
    if (cur >= 0) atomicAdd(&g_hg[cur * D + t], acc);
}

__global__ void gcnt_kernel(const int* __restrict__ gid, int n_nodes) {
    int g = threadIdx.x;
    if (g >= NG) return;
    int lo = 0, hi = n_nodes;
    while (lo < hi) { int mid = (lo + hi) >> 1; if (gid[mid] < g) lo = mid + 1; else hi = mid; }
    int lb0 = lo;
    lo = 0; hi = n_nodes;
    while (lo < hi) { int mid = (lo + hi) >> 1; if (gid[mid] < g + 1) lo = mid + 1; else hi = mid; }
    g_gcnt[g] = lo - lb0;
}

// ---------------- final FC + log_softmax ----------------
__global__ void final_kernel(const float* __restrict__ Wfc, const float* __restrict__ bfc,
                             float* __restrict__ out) {
    int g = threadIdx.x;
    if (g >= NG) return;
    float cnt = (float)g_gcnt[g];
    if (cnt < 1.f) cnt = 1.f;
    float inv = 1.0f / cnt;
    float l0 = bfc[0], l1 = bfc[1];
    for (int k = 0; k < D; k++) {
        float v = g_hg[g * D + k] * inv;
        l0 += v * Wfc[k * 2 + 0];
        l1 += v * Wfc[k * 2 + 1];
    }
    float mx = fmaxf(l0, l1);
    float lse = mx + logf(expf(l0 - mx) + expf(l1 - mx));
    out[g * 2 + 0] = l0 - lse;
    out[g * 2 + 1] = l1 - lse;
}

// ---------------- launch ----------------
extern "C" void kernel_launch(void* const* d_in, const int* in_sizes, int n_in,
                              void* d_out, int out_size) {
    const float* h   = (const float*)d_in[0];
    const int*   src = (const int*)d_in[1];
    const int*   dst = (const int*)d_in[2];
    const int*   gid = (const int*)d_in[3];
    const float* W1  = (const float*)d_in[4];
    const float* al1 = (const float*)d_in[5];
    const float* ar1 = (const float*)d_in[6];
    const float* b1  = (const float*)d_in[7];
    const float* W2  = (const float*)d_in[8];
    const float* al2 = (const float*)d_in[9];
    const float* ar2 = (const float*)d_in[10];
    const float* b2  = (const float*)d_in[11];
    const float* Wfc = (const float*)d_in[12];
    const float* bfc = (const float*)d_in[13];
    float* out = (float*)d_out;

    int n_nodes = in_sizes[3];
    int E = in_sizes[1];
    if (n_nodes > NMAX) n_nodes = NMAX;
    if (E > EMAX) E = EMAX;

    static bool attr_done = false;
    if (!attr_done) {
        cudaFuncSetAttribute(gemm_kernel, cudaFuncAttributeMaxDynamicSharedMemorySize,
                             (D * D + 64 * D) * sizeof(float));
        attr_done = true;
    }
    size_t gemm_smem = (size_t)(D * D + 64 * D) * sizeof(float);

    zero_kernel<<<256, 256>>>(n_nodes);
    hist_kernel<<<512, 256>>>(dst, E);
    scan_kernel<<<1, 1024>>>(n_nodes);
    scatter_kernel<<<512, 256>>>(src, dst, E);

    int gemm_grid = (n_nodes + 63) / 64;
    int warp_grid = (n_nodes * 32 + 255) / 256;

    // layer 1
    gemm_kernel<<<gemm_grid, 256, gemm_smem>>>(h, W1, g_feat, n_nodes);
    el_er_kernel<<<warp_grid, 256>>>(g_feat, al1, ar1, n_nodes);
    stats_kernel<<<warp_grid, 256>>>(n_nodes);
    spmm_kernel<<<warp_grid, 256>>>(g_feat, b1, g_x, n_nodes);

    // layer 2
    gemm_kernel<<<gemm_grid, 256, gemm_smem>>>(g_x, W2, g_feat, n_nodes);
    el_er_kernel<<<warp_grid, 256>>>(g_feat, al2, ar2, n_nodes);
    stats_kernel<<<warp_grid, 256>>>(n_nodes);
    spmm_kernel<<<warp_grid, 256>>>(g_feat, b2, g_x, n_nodes);

    // pooling + classifier
    pool_kernel<<<(n_nodes + 255) / 256, 128>>>(g_x, gid, n_nodes);
    gcnt_kernel<<<1, 64>>>(gid, n_nodes);
    final_kernel<<<1, 64>>>(Wfc, bfc, out);
}

// round 7
// speedup vs baseline: 3.4993x; 3.4993x over previous
#include <cuda_runtime.h>
#include <cuda_bf16.h>
#include <math.h>

#define NMAX 100000
#define EMAX 1600000
#define D    128
#define D4   32
#define NG   64
#define NEG_SLOPE 0.2f

// ---------------- scratch (static device globals; no allocs allowed) ----------------
__device__ float g_feat[NMAX * D];            // x @ W for current layer (fp32)
__device__ __nv_bfloat16 g_featb[NMAX * D];   // bf16 copy for the edge gather
__device__ float g_x[NMAX * D];               // layer output / next layer input
__device__ float g_el[NMAX];
__device__ float g_er[NMAX];
__device__ float g_inv[NMAX];                 // 1 / softmax denominator per dst
__device__ int   g_counts[NMAX];
__device__ int   g_offsets[NMAX + 1];
__device__ int   g_cursor[NMAX];
__device__ int   g_esrc[EMAX];                // src node of each edge, sorted by dst
__device__ float g_ew[EMAX];                  // per-edge scratch: e, then exp(e-m)
__device__ float g_hg[NG * D];
__device__ int   g_gcnt[NG];

// ---------------- zeroing ----------------
__global__ void zero_kernel(int n_nodes) {
    int i = blockIdx.x * blockDim.x + threadIdx.x;
    int stride = gridDim.x * blockDim.x;
    for (int k = i; k < n_nodes; k += stride) g_counts[k] = 0;
    for (int k = i; k < NG * D; k += stride) g_hg[k] = 0.0f;
}

// ---------------- CSR build ----------------
__global__ void hist_kernel(const int* __restrict__ dst, int E) {
    int i = blockIdx.x * blockDim.x + threadIdx.x;
    int stride = gridDim.x * blockDim.x;
    for (int e = i; e < E; e += stride) atomicAdd(&g_counts[dst[e]], 1);
}

__global__ void scan_kernel(int n_nodes) {
    __shared__ int sums[1024];
    int t = threadIdx.x;
    int chunk = (n_nodes + 1023) / 1024;
    int begin = t * chunk;
    int end = begin + chunk; if (end > n_nodes) end = n_nodes;
    int s = 0;
    for (int i = begin; i < end; i++) s += g_counts[i];
    sums[t] = s;
    __syncthreads();
    for (int off = 1; off < 1024; off <<= 1) {
        int v = (t >= off) ? sums[t - off] : 0;
        __syncthreads();
        sums[t] += v;
        __syncthreads();
    }
    int run = (t > 0) ? sums[t - 1] : 0;
    for (int i = begin; i < end; i++) {
        int c = g_counts[i];
        g_offsets[i] = run;
        g_cursor[i]  = run;
        run += c;
    }
    if (t == 1023) g_offsets[n_nodes] = sums[1023];
}

__global__ void scatter_kernel(const int* __restrict__ src, const int* __restrict__ dst, int E) {
    int i = blockIdx.x * blockDim.x + threadIdx.x;
    int stride = gridDim.x * blockDim.x;
    for (int e = i; e < E; e += stride) {
        int d = dst[e];
        int pos = atomicAdd(&g_cursor[d], 1);
        g_esrc[pos] = src[e];
    }
}

// ---------------- PROFILER PROBE: reproduces the spmm gather pattern ----------------
// Warp per 16 consecutive edges, gathers 256B bf16 rows by raw src index.
// Writes to g_feat, which gemm1 fully overwrites -> no effect on output.
// Placed at launch slot 3 so ncu (-s 5 -c 1 after 2 harness launches) profiles it.
__global__ __launch_bounds__(256) void probe_gather(const int* __restrict__ src, int E, int n_nodes) {
    int w = (blockIdx.x * blockDim.x + threadIdx.x) >> 5;
    int lane = threadIdx.x & 31;
    int base = w * 16;
    if (base >= E) return;
    int end = base + 16; if (end > E) end = E;
    const uint2* fb = (const uint2*)g_featb;
    float acc = 0.f;
    int i = base;
    for (; i + 4 <= end; i += 4) {
        int s0 = src[i + 0], s1 = src[i + 1], s2 = src[i + 2], s3 = src[i + 3];
        uint2 v0 = fb[s0 * 32 + lane];
        uint2 v1 = fb[s1 * 32 + lane];
        uint2 v2 = fb[s2 * 32 + lane];
        uint2 v3 = fb[s3 * 32 + lane];
        acc += (float)(v0.x ^ v1.y) + (float)(v2.x ^ v3.y);
    }
    for (; i < end; i++) {
        uint2 v = fb[src[i] * 32 + lane];
        acc += (float)(v.x ^ v.y);
    }
    if (w < n_nodes) g_feat[w * 32 + lane] = acc;   // dummy sink, overwritten by gemm1
}

// ---------------- GEMM: out[N,128] = X[N,128] @ W[128,128] ----------------
__global__ __launch_bounds__(256) void gemm_kernel(const float* __restrict__ X,
                                                   const float* __restrict__ W,
                                                   float* __restrict__ out, int n_rows) {
    extern __shared__ float sm[];
    float* Ws = sm;            // 128*128 floats = 64KB
    float* Xs = sm + D * D;    // 64*128 floats  = 32KB
    int tid = threadIdx.x;
    int row0 = blockIdx.x * 64;

    for (int i = tid; i < (D * D) / 4; i += 256)
        ((float4*)Ws)[i] = ((const float4*)W)[i];
    for (int i = tid; i < (64 * D) / 4; i += 256) {
        int r = i / D4;
        int c = i % D4;
        int gr = row0 + r;
        float4 v = make_float4(0.f, 0.f, 0.f, 0.f);
        if (gr < n_rows) v = ((const float4*)X)[gr * D4 + c];
        ((float4*)Xs)[i] = v;
    }
    __syncthreads();

    int tx = tid & 15;
    int ty = tid >> 4;
    int c0 = tx * 8;
    float acc[4][8];
#pragma unroll
    for (int r = 0; r < 4; r++)
#pragma unroll
        for (int c = 0; c < 8; c++) acc[r][c] = 0.f;

#pragma unroll 4
    for (int k = 0; k < D; k++) {
        float a0 = Xs[(ty * 4 + 0) * D + k];
        float a1 = Xs[(ty * 4 + 1) * D + k];
        float a2 = Xs[(ty * 4 + 2) * D + k];
        float a3 = Xs[(ty * 4 + 3) * D + k];
        float4 b0 = *(float4*)&Ws[k * D + c0];
        float4 b1 = *(float4*)&Ws[k * D + c0 + 4];
        float bb[8] = {b0.x, b0.y, b0.z, b0.w, b1.x, b1.y, b1.z, b1.w};
#pragma unroll
        for (int c = 0; c < 8; c++) {
            acc[0][c] += a0 * bb[c];
            acc[1][c] += a1 * bb[c];
            acc[2][c] += a2 * bb[c];
            acc[3][c] += a3 * bb[c];
        }
    }

#pragma unroll
    for (int r = 0; r < 4; r++) {
        int gr = row0 + ty * 4 + r;
        if (gr < n_rows) {
            float4 v0 = make_float4(acc[r][0], acc[r][1], acc[r][2], acc[r][3]);
            float4 v1 = make_float4(acc[r][4], acc[r][5], acc[r][6], acc[r][7]);
            ((float4*)out)[gr * D4 + tx * 2 + 0] = v0;
            ((float4*)out)[gr * D4 + tx * 2 + 1] = v1;
        }
    }
}

// ---------------- el/er dot products + bf16 feature conversion (fused) ----------------
__global__ __launch_bounds__(256) void el_er_kernel(const float* __restrict__ feat,
                             const float* __restrict__ al, const float* __restrict__ ar,
                             int n_nodes) {
    int w = (blockIdx.x * blockDim.x + threadIdx.x) >> 5;
    int lane = threadIdx.x & 31;
    if (w >= n_nodes) return;
    float4 f = ((const float4*)feat)[w * D4 + lane];

    // bf16 copy for the gather path
    __nv_bfloat162 h0 = __floats2bfloat162_rn(f.x, f.y);
    __nv_bfloat162 h1 = __floats2bfloat162_rn(f.z, f.w);
    uint2 packed;
    packed.x = *(unsigned int*)&h0;
    packed.y = *(unsigned int*)&h1;
    ((uint2*)g_featb)[w * D4 + lane] = packed;

    float4 a = ((const float4*)al)[lane];
    float4 b = ((const float4*)ar)[lane];
    float sl = f.x * a.x + f.y * a.y + f.z * a.z + f.w * a.w;
    float sr = f.x * b.x + f.y * b.y + f.z * b.z + f.w * b.w;
#pragma unroll
    for (int o = 16; o > 0; o >>= 1) {
        sl += __shfl_xor_sync(0xffffffffu, sl, o);
        sr += __shfl_xor_sync(0xffffffffu, sr, o);
    }
    if (lane == 0) { g_el[w] = sl; g_er[w] = sr; }
}

// ---------------- attention stats: per-dst max + softmax denominator ----------------
__global__ __launch_bounds__(256) void stats_kernel(int n_nodes) {
    int w = (blockIdx.x * blockDim.x + threadIdx.x) >> 5;
    int lane = threadIdx.x & 31;
    if (w >= n_nodes) return;
    int start = g_offsets[w];
    int end = g_offsets[w + 1];
    if (end == start) return;
    float erd = g_er[w];

    float m = -1e30f;
    for (int i = start + lane; i < end; i += 32) {
        int s = g_esrc[i];
        float e = g_el[s] + erd;
        e = e > 0.f ? e : NEG_SLOPE * e;
        g_ew[i] = e;
        m = fmaxf(m, e);
    }
#pragma unroll
    for (int o = 16; o > 0; o >>= 1) m = fmaxf(m, __shfl_xor_sync(0xffffffffu, m, o));

    float ss = 0.f;
    for (int i = start + lane; i < end; i += 32) {
        float ex = __expf(g_ew[i] - m);
        g_ew[i] = ex;
        ss += ex;
    }
#pragma unroll
    for (int o = 16; o > 0; o >>= 1) ss += __shfl_xor_sync(0xffffffffu, ss, o);
    if (lane == 0) g_inv[w] = 1.0f / ss;
}

// ---------------- weighted SpMM over bf16 features ----------------
// out[dst] = relu((sum_e w_e * featb[src_e]) * inv + b); warp per dst, 4-edge unroll.
__global__ __launch_bounds__(256) void spmm_kernel(const float* __restrict__ bias,
                                                   float* __restrict__ out, int n_nodes) {
    int w = (blockIdx.x * blockDim.x + threadIdx.x) >> 5;
    int lane = threadIdx.x & 31;
    if (w >= n_nodes) return;
    int start = g_offsets[w];
    int end = g_offsets[w + 1];

    const uint2* fb = (const uint2*)g_featb;
    float4 acc = make_float4(0.f, 0.f, 0.f, 0.f);

    int i = start;
    for (; i + 4 <= end; i += 4) {
        int s0 = g_esrc[i + 0];
        int s1 = g_esrc[i + 1];
        int s2 = g_esrc[i + 2];
        int s3 = g_esrc[i + 3];
        float w0 = g_ew[i + 0];
        float w1 = g_ew[i + 1];
        float w2 = g_ew[i + 2];
        float w3 = g_ew[i + 3];
        uint2 v0 = fb[s0 * D4 + lane];
        uint2 v1 = fb[s1 * D4 + lane];
        uint2 v2 = fb[s2 * D4 + lane];
        uint2 v3 = fb[s3 * D4 + lane];
        float2 a0 = __bfloat1622float2(*(__nv_bfloat162*)&v0.x);
        float2 b0 = __bfloat1622float2(*(__nv_bfloat162*)&v0.y);
        float2 a1 = __bfloat1622float2(*(__nv_bfloat162*)&v1.x);
        float2 b1 = __bfloat1622float2(*(__nv_bfloat162*)&v1.y);
        float2 a2 = __bfloat1622float2(*(__nv_bfloat162*)&v2.x);
        float2 b2 = __bfloat1622float2(*(__nv_bfloat162*)&v2.y);
        float2 a3 = __bfloat1622float2(*(__nv_bfloat162*)&v3.x);
        float2 b3 = __bfloat1622float2(*(__nv_bfloat162*)&v3.y);
        acc.x += w0 * a0.x + w1 * a1.x + w2 * a2.x + w3 * a3.x;
        acc.y += w0 * a0.y + w1 * a1.y + w2 * a2.y + w3 * a3.y;
        acc.z += w0 * b0.x + w1 * b1.x + w2 * b2.x + w3 * b3.x;
        acc.w += w0 * b0.y + w1 * b1.y + w2 * b2.y + w3 * b3.y;
    }
    for (; i < end; i++) {
        int s = g_esrc[i];
        float ww = g_ew[i];
        uint2 v = fb[s * D4 + lane];
        float2 a = __bfloat1622float2(*(__nv_bfloat162*)&v.x);
        float2 b = __bfloat1622float2(*(__nv_bfloat162*)&v.y);
        acc.x += ww * a.x;
        acc.y += ww * a.y;
        acc.z += ww * b.x;
        acc.w += ww * b.y;
    }

    float4 b = ((const float4*)bias)[lane];
    float4 o4;
    if (end > start) {
        float inv = g_inv[w];
        o4.x = fmaxf(acc.x * inv + b.x, 0.f);
        o4.y = fmaxf(acc.y * inv + b.y, 0.f);
        o4.z = fmaxf(acc.z * inv + b.z, 0.f);
        o4.w = fmaxf(acc.w * inv + b.w, 0.f);
    } else {
        o4.x = fmaxf(b.x, 0.f);
        o4.y = fmaxf(b.y, 0.f);
        o4.z = fmaxf(b.z, 0.f);
        o4.w = fmaxf(b.w, 0.f);
    }
    ((float4*)out)[w * D4 + lane] = o4;
}

// ---------------- pooling: graph_id is sorted, running per-block accumulate ----------------
__global__ void pool_kernel(const float* __restrict__ x, const int* __restrict__ gid,
                            int n_nodes) {
    int t = threadIdx.x;          // 0..127, one feature column each
    int n0 = blockIdx.x * 64;
    float acc = 0.f;
    int cur = -1;
    for (int i = 0; i < 64; i++) {
        int n = n0 + i;
        if (n >= n_nodes) break;
        int g = gid[n];
        if (g != cur) {
            if (cur >= 0) atomicAdd(&g_hg[cur * D + t], acc);
            acc = 0.f;
            cur = g;
        }
        acc += x[n * D + t];
    }
    if (cur >= 0) atomicAdd(&g_hg[cur * D + t], acc);
}

__global__ void gcnt_kernel(const int* __restrict__ gid, int n_nodes) {
    int g = threadIdx.x;
    if (g >= NG) return;
    int lo = 0, hi = n_nodes;
    while (lo < hi) { int mid = (lo + hi) >> 1; if (gid[mid] < g) lo = mid + 1; else hi = mid; }
    int lb0 = lo;
    lo = 0; hi = n_nodes;
    while (lo < hi) { int mid = (lo + hi) >> 1; if (gid[mid] < g + 1) lo = mid + 1; else hi = mid; }
    g_gcnt[g] = lo - lb0;
}

// ---------------- final FC + log_softmax ----------------
__global__ void final_kernel(const float* __restrict__ Wfc, const float* __restrict__ bfc,
                             float* __restrict__ out) {
    int g = threadIdx.x;
    if (g >= NG) return;
    float cnt = (float)g_gcnt[g];
    if (cnt < 1.f) cnt = 1.f;
    float inv = 1.0f / cnt;
    float l0 = bfc[0], l1 = bfc[1];
    for (int k = 0; k < D; k++) {
        float v = g_hg[g * D + k] * inv;
        l0 += v * Wfc[k * 2 + 0];
        l1 += v * Wfc[k * 2 + 1];
    }
    float mx = fmaxf(l0, l1);
    float lse = mx + logf(expf(l0 - mx) + expf(l1 - mx));
    out[g * 2 + 0] = l0 - lse;
    out[g * 2 + 1] = l1 - lse;
}

// ---------------- launch ----------------
extern "C" void kernel_launch(void* const* d_in, const int* in_sizes, int n_in,
                              void* d_out, int out_size) {
    const float* h   = (const float*)d_in[0];
    const int*   src = (const int*)d_in[1];
    const int*   dst = (const int*)d_in[2];
    const int*   gid = (const int*)d_in[3];
    const float* W1  = (const float*)d_in[4];
    const float* al1 = (const float*)d_in[5];
    const float* ar1 = (const float*)d_in[6];
    const float* b1  = (const float*)d_in[7];
    const float* W2  = (const float*)d_in[8];
    const float* al2 = (const float*)d_in[9];
    const float* ar2 = (const float*)d_in[10];
    const float* b2  = (const float*)d_in[11];
    const float* Wfc = (const float*)d_in[12];
    const float* bfc = (const float*)d_in[13];
    float* out = (float*)d_out;

    int n_nodes = in_sizes[3];
    int E = in_sizes[1];
    if (n_nodes > NMAX) n_nodes = NMAX;
    if (E > EMAX) E = EMAX;

    static bool attr_done = false;
    if (!attr_done) {
        cudaFuncSetAttribute(gemm_kernel, cudaFuncAttributeMaxDynamicSharedMemorySize,
                             (D * D + 64 * D) * sizeof(float));
        attr_done = true;
    }
    size_t gemm_smem = (size_t)(D * D + 64 * D) * sizeof(float);

    int gemm_grid = (n_nodes + 63) / 64;
    int warp_grid = (n_nodes * 32 + 255) / 256;
    int probe_grid = ((E + 15) / 16 + 7) / 8;

    zero_kernel<<<256, 256>>>(n_nodes);                  // slot 0
    hist_kernel<<<512, 256>>>(dst, E);                   // slot 1
    scan_kernel<<<1, 1024>>>(n_nodes);                   // slot 2
    probe_gather<<<probe_grid, 256>>>(src, E, n_nodes);  // slot 3  <- profiled by ncu
    scatter_kernel<<<512, 256>>>(src, dst, E);           // slot 4

    // layer 1
    gemm_kernel<<<gemm_grid, 256, gemm_smem>>>(h, W1, g_feat, n_nodes);
    el_er_kernel<<<warp_grid, 256>>>(g_feat, al1, ar1, n_nodes);
    stats_kernel<<<warp_grid, 256>>>(n_nodes);
    spmm_kernel<<<warp_grid, 256>>>(b1, g_x, n_nodes);

    // layer 2
    gemm_kernel<<<gemm_grid, 256, gemm_smem>>>(g_x, W2, g_feat, n_nodes);
    el_er_kernel<<<warp_grid, 256>>>(g_feat, al2, ar2, n_nodes);
    stats_kernel<<<warp_grid, 256>>>(n_nodes);
    spmm_kernel<<<warp_grid, 256>>>(b2, g_x, n_nodes);

    // pooling + classifier
    pool_kernel<<<(n_nodes + 63) / 64, 128>>>(g_x, gid, n_nodes);
    gcnt_kernel<<<1, 64>>>(gid, n_nodes);
    final_kernel<<<1, 64>>>(Wfc, bfc, out);
}